// round 13
// baseline (speedup 1.0000x reference)
#include <cuda_runtime.h>
#include <cuda_fp16.h>
#include <math.h>

typedef unsigned int u32;

// Problem constants
#define B_      2
#define S_      4096
#define E_      2048
#define NH_     16
#define HD_     128
#define NKV_    4
#define KVOUT_  1024
#define QKVN_   3072
#define WINDOW_ 512
#define NMETA_  16

// ---------------------------------------------------------------------------
// Scratch (device globals)
// ---------------------------------------------------------------------------
__device__ __half g_x16 [B_ * S_ * E_];
__device__ __half g_q16 [B_ * S_ * E_];
__device__ __half g_kv16[B_ * S_ * KVOUT_];
__device__ __half g_y16 [B_ * S_ * E_];
__device__ __half g_wqkvt[QKVN_ * E_];
__device__ __half g_wot [E_ * E_];
__device__ float  g_bqkv[QKVN_];
__device__ float2 g_ropetab[S_ * 64];

// ---------------------------------------------------------------------------
// Helpers
// ---------------------------------------------------------------------------
__device__ __forceinline__ u32 smem_u32(const void* p) {
    u32 a;
    asm("{ .reg .u64 t; cvta.to.shared.u64 t, %1; cvt.u32.u64 %0, t; }"
        : "=r"(a) : "l"(p));
    return a;
}

__device__ __forceinline__ void mma16816(float* d, const u32* a, const u32* b)
{
    asm volatile(
        "mma.sync.aligned.m16n8k16.row.col.f32.f16.f16.f32 "
        "{%0,%1,%2,%3}, {%4,%5,%6,%7}, {%8,%9}, {%0,%1,%2,%3};"
        : "+f"(d[0]), "+f"(d[1]), "+f"(d[2]), "+f"(d[3])
        : "r"(a[0]), "r"(a[1]), "r"(a[2]), "r"(a[3]), "r"(b[0]), "r"(b[1]));
}

__device__ __forceinline__ void ldsm_x4(u32* r, u32 addr)
{
    asm volatile("ldmatrix.sync.aligned.m8n8.x4.shared.b16 {%0,%1,%2,%3}, [%4];"
        : "=r"(r[0]), "=r"(r[1]), "=r"(r[2]), "=r"(r[3]) : "r"(addr));
}

__device__ __forceinline__ void ldsm_x4_t(u32* r, u32 addr)
{
    asm volatile("ldmatrix.sync.aligned.m8n8.x4.trans.shared.b16 {%0,%1,%2,%3}, [%4];"
        : "=r"(r[0]), "=r"(r[1]), "=r"(r[2]), "=r"(r[3]) : "r"(addr));
}

__device__ __forceinline__ u32 packh2(float x, float y)
{
    __half2 h = __floats2half2_rn(x, y);
    return *(u32*)&h;
}

#define CP_ASYNC16(dst, src) \
    asm volatile("cp.async.cg.shared.global [%0], [%1], 16;" :: "r"(dst), "l"(src))
#define CP_ASYNC16Z(dst, src, sz) \
    asm volatile("cp.async.cg.shared.global [%0], [%1], 16, %2;" \
                 :: "r"(dst), "l"(src), "r"(sz))
#define CP_COMMIT() asm volatile("cp.async.commit_group;")
#define CP_WAIT1()  asm volatile("cp.async.wait_group 1;")
#define CP_WAIT0()  asm volatile("cp.async.wait_group 0;")

// ---------------------------------------------------------------------------
// Prep kernels
// ---------------------------------------------------------------------------
__global__ void convert_kernel(const float* __restrict__ in,
                               __half* __restrict__ out, int n4)
{
    int i = blockIdx.x * 256 + threadIdx.x;
    if (i >= n4) return;
    float4 v = ((const float4*)in)[i];
    u32* O = (u32*)out;
    O[i * 2]     = packh2(v.x, v.y);
    O[i * 2 + 1] = packh2(v.z, v.w);
}

// One launch: z=0..2 -> weight transposes, z=3 -> rope table + bias concat
__global__ void prep_kernel(const float* __restrict__ Wq,
                            const float* __restrict__ Wkv,
                            const float* __restrict__ Wo,
                            const float* __restrict__ bq,
                            const float* __restrict__ bkv,
                            __half* __restrict__ wqkvt,
                            __half* __restrict__ wot,
                            float* __restrict__ bqkv,
                            float2* __restrict__ tab)
{
    int z = blockIdx.z;
    if (z < 3) {
        const float* W;
        __half* T;
        int N;
        if (z == 0)      { W = Wq;  T = wqkvt;                   N = E_; }
        else if (z == 1) { W = Wkv; T = wqkvt + (size_t)E_ * E_; N = KVOUT_; }
        else             { W = Wo;  T = wot;                     N = E_; }
        const int K = E_;
        __shared__ float t[32][33];
        int n0 = blockIdx.x * 32, k0 = blockIdx.y * 32;
        if (n0 >= N) return;
        for (int i = threadIdx.y; i < 32; i += 8)
            t[i][threadIdx.x] = W[(size_t)(k0 + i) * N + n0 + threadIdx.x];
        __syncthreads();
        for (int i = threadIdx.y; i < 32; i += 8)
            T[(size_t)(n0 + i) * K + k0 + threadIdx.x] =
                __float2half_rn(t[threadIdx.x][i]);
    } else {
        int t = (blockIdx.y * gridDim.x + blockIdx.x) * 256
                + threadIdx.y * 32 + threadIdx.x;
        if (t < S_ * 64) {
            int pos = t >> 6, i = t & 63;
            float inv = (float)exp(-(double)i * (9.210340371976184 / 64.0));
            float ang = (float)pos * inv;
            tab[t] = make_float2(cosf(ang), sinf(ang));
        } else {
            int u = t - S_ * 64;
            if (u < E_) bqkv[u] = bq[u];
            else if (u < QKVN_) bqkv[u] = bkv[u - E_];
        }
    }
}

// ---------------------------------------------------------------------------
// mma.sync fp16 GEMM. Block 256x128x64 (halves L2 traffic vs 128x128),
// 8 warps (4m x 2n) of 64x64 tiles, cp.async 3-stage, 1 CTA/SM.
// mode 0: fp32 out. mode 1: fused qkv out (rope cols < 2560).
// ---------------------------------------------------------------------------
#define BKP        72
#define TILE_A_ELEM (256 * BKP)
#define TILE_B_ELEM (128 * BKP)
#define STAGE_ELEM  (TILE_A_ELEM + TILE_B_ELEM)
#define GT_SMEM     (3 * STAGE_ELEM * 2)

__global__ __launch_bounds__(256, 1) void mma_gemm_kernel(
    const __half* __restrict__ A, const __half* __restrict__ Bm,
    const float* __restrict__ bias, float* __restrict__ Cf,
    __half* __restrict__ Cq, __half* __restrict__ Ckv,
    const float2* __restrict__ tab, int M, int N, int K, int mode)
{
    extern __shared__ __half sm[];
    const u32 sbase = smem_u32(sm);
    const int tid = threadIdx.x;
    const int wid = tid >> 5, lane = tid & 31;
    const int wm = wid & 3, wn = wid >> 2;       // 4m x 2n warp grid
    const int m0 = blockIdx.y * 256;
    const int n0 = blockIdx.x * 128;
    const int g  = lane >> 2;
    const int c0 = (lane & 3) * 2;
    const int lrow = lane & 7, grp = lane >> 3;

    auto load_stage = [&](int c, int stage) {
        const int k0 = c * 64;
        const u32 sb = sbase + stage * STAGE_ELEM * 2;
        // A: 256 rows x 64 cols -> 8 ld16/thread
#pragma unroll
        for (int i = 0; i < 8; i++) {
            int idx = tid + i * 256;
            int row = idx >> 3, q8 = idx & 7;
            u32 soff = (u32)(row * BKP + q8 * 8) * 2;
            size_t ga = (size_t)(m0 + row) * K + k0 + q8 * 8;
            CP_ASYNC16(sb + soff, (const char*)(A + ga));
        }
        // B: 128 rows x 64 cols -> 4 ld16/thread
#pragma unroll
        for (int i = 0; i < 4; i++) {
            int idx = tid + i * 256;
            int row = idx >> 3, q8 = idx & 7;
            u32 soff = (u32)(row * BKP + q8 * 8) * 2;
            size_t gb = (size_t)(n0 + row) * K + k0 + q8 * 8;
            CP_ASYNC16(sb + TILE_A_ELEM * 2 + soff, (const char*)(Bm + gb));
        }
    };

    float acc[4][8][4];
#pragma unroll
    for (int i = 0; i < 4; i++)
#pragma unroll
        for (int j = 0; j < 8; j++)
#pragma unroll
            for (int e = 0; e < 4; e++) acc[i][j][e] = 0.f;

    const int nc = K >> 6;
    load_stage(0, 0); CP_COMMIT();
    load_stage(1, 1); CP_COMMIT();

    for (int c = 0; c < nc; c++) {
        if (c + 1 < nc) CP_WAIT1(); else CP_WAIT0();
        __syncthreads();
        if (c + 2 < nc) {
            load_stage(c + 2, (c + 2) % 3);
            CP_COMMIT();
        }

        const u32 st = sbase + (u32)((c % 3) * STAGE_ELEM) * 2;
        const u32 sA = st;
        const u32 sB = st + TILE_A_ELEM * 2;

#pragma unroll
        for (int kh = 0; kh < 4; kh++) {
            const int kk = kh * 16;
            u32 bfr[8][2];
#pragma unroll
            for (int nfp = 0; nfp < 4; nfp++) {
                u32 off = (u32)((wn * 64 + nfp * 16 + (grp >> 1) * 8 + lrow) * BKP
                                + kk + (grp & 1) * 8) * 2;
                ldsm_x4(&bfr[nfp * 2][0], sB + off);
            }
#pragma unroll
            for (int mf = 0; mf < 4; mf++) {
                u32 offa = (u32)((wm * 64 + mf * 16 + (grp & 1) * 8 + lrow) * BKP
                                 + kk + (grp >> 1) * 8) * 2;
                u32 a[4];
                ldsm_x4(a, sA + offa);
#pragma unroll
                for (int nf = 0; nf < 8; nf++)
                    mma16816(acc[mf][nf], a, bfr[nf]);
            }
        }
    }

    // Epilogue
#pragma unroll
    for (int mf = 0; mf < 4; mf++) {
        int row0 = m0 + wm * 64 + mf * 16 + g;
        int pos0 = row0 & (S_ - 1);
        int pos1 = (row0 + 8) & (S_ - 1);
#pragma unroll
        for (int nf = 0; nf < 8; nf++) {
            int col = n0 + wn * 64 + nf * 8 + c0;
            float b0 = bias[col], b1 = bias[col + 1];
            float v0 = acc[mf][nf][0] + b0, v1 = acc[mf][nf][1] + b1;
            float v2 = acc[mf][nf][2] + b0, v3 = acc[mf][nf][3] + b1;
            if (mode == 0) {
                *(float2*)(Cf + (size_t)row0 * N + col)       = make_float2(v0, v1);
                *(float2*)(Cf + (size_t)(row0 + 8) * N + col) = make_float2(v2, v3);
            } else {
                bool do_rope = (col < 2560);
                if (do_rope) {
                    int ti = (col & 127) >> 1;
                    float2 cs0 = tab[pos0 * 64 + ti];
                    float2 cs1 = tab[pos1 * 64 + ti];
                    float t0 = v0, t1 = v1;
                    v0 = t0 * cs0.x - t1 * cs0.y;
                    v1 = t1 * cs0.x + t0 * cs0.y;
                    float t2 = v2, t3 = v3;
                    v2 = t2 * cs1.x - t3 * cs1.y;
                    v3 = t3 * cs1.x + t2 * cs1.y;
                }
                if (col < E_) {
                    *(u32*)(Cq + (size_t)row0 * E_ + col)       = packh2(v0, v1);
                    *(u32*)(Cq + (size_t)(row0 + 8) * E_ + col) = packh2(v2, v3);
                } else {
                    int c2 = col - E_;
                    *(u32*)(Ckv + (size_t)row0 * KVOUT_ + c2)       = packh2(v0, v1);
                    *(u32*)(Ckv + (size_t)(row0 + 8) * KVOUT_ + c2) = packh2(v2, v3);
                }
            }
        }
    }
}

// ---------------------------------------------------------------------------
// Attention: mma.sync fp16, 3-stage cp.async K/V pipeline, mask hoisting,
// exp2-domain softmax. (unchanged from R12)
// ---------------------------------------------------------------------------
#define AT_BKP   136
#define AT_TILE  (64 * AT_BKP)
#define AT_STAGE (2 * AT_TILE)
#define ATT_SMEM (3 * AT_STAGE * 2)

__global__ __launch_bounds__(128, 2) void attn_mma_kernel(
    const __half* __restrict__ q16, const __half* __restrict__ kv16,
    __half* __restrict__ y16)
{
    extern __shared__ __half sm[];
    const u32 smb = smem_u32(sm);
    const int tid = threadIdx.x;
    const int w = tid >> 5, lane = tid & 31;
    const int g = lane >> 2, c0 = (lane & 3) * 2;
    const int lrow = lane & 7, grp = lane >> 3;
    const int bhp = blockIdx.y;
    const int b = bhp >> 4, h = bhp & 15;
    const int kv_h = h >> 2;
    const int q0 = blockIdx.x << 6;
    int ls = q0 - WINDOW_ + 1; if (ls < NMETA_) ls = NMETA_;
    const int kend = q0 + 64;
    const float scale2 = 0.088388347648318447f * 1.4426950408889634f;

#pragma unroll
    for (int it = 0; it < 8; it++) {
        int fi = tid + it * 128;
        int r = fi >> 4, q8 = fi & 15;
        size_t ga = ((size_t)(b * S_ + q0 + r) * NH_ + h) * HD_ + q8 * 8;
        CP_ASYNC16(smb + (u32)(r * AT_BKP + q8 * 8) * 2, (const char*)(q16 + ga));
    }
    CP_COMMIT(); CP_WAIT0();
    __syncthreads();

    u32 qf[8][4];
#pragma unroll
    for (int ks = 0; ks < 8; ks++) {
        u32 off = (u32)((w * 16 + (grp & 1) * 8 + lrow) * AT_BKP
                        + ks * 16 + (grp >> 1) * 8) * 2;
        ldsm_x4(qf[ks], smb + off);
    }
    __syncthreads();

    auto load_tile = [&](int t, int stage) {
        int kb = (t == 0) ? 0 : (ls + ((t - 1) << 6));
        int kc = (t == 0) ? NMETA_ : (kend - kb);
        if (kc > 64) kc = 64;
        u32 sK = smb + (u32)(stage * AT_STAGE) * 2;
        u32 sV = sK + AT_TILE * 2;
#pragma unroll
        for (int it = 0; it < 8; it++) {
            int fi = tid + it * 128;
            int r = fi >> 4, q8 = fi & 15;
            int sz = (r < kc) ? 16 : 0;
            int rr = (r < kc) ? r : 0;
            size_t base = (size_t)(b * S_ + kb + rr) * 1024 + kv_h * 128 + q8 * 8;
            u32 off = (u32)(r * AT_BKP + q8 * 8) * 2;
            CP_ASYNC16Z(sK + off, (const char*)(kv16 + base), sz);
            CP_ASYNC16Z(sV + off, (const char*)(kv16 + base + 512), sz);
        }
    };

    float m0 = -1e30f, m1 = -1e30f, l0 = 0.f, l1 = 0.f;
    float o[16][4];
#pragma unroll
    for (int i = 0; i < 16; i++)
#pragma unroll
        for (int e = 0; e < 4; e++) o[i][e] = 0.f;

    const int qp0 = q0 + w * 16 + g;
    const int qp1 = qp0 + 8;
    const int nT = 1 + ((kend - ls + 63) >> 6);

    load_tile(0, 0); CP_COMMIT();
    load_tile(1, 1); CP_COMMIT();

    for (int t = 0; t < nT; t++) {
        if (t + 1 < nT) CP_WAIT1(); else CP_WAIT0();
        __syncthreads();
        if (t + 2 < nT) {
            load_tile(t + 2, (t + 2) % 3);
            CP_COMMIT();
        }

        const u32 sK = smb + (u32)((t % 3) * AT_STAGE) * 2;
        const u32 sV = sK + AT_TILE * 2;
        const int kbase = (t == 0) ? 0 : (ls + ((t - 1) << 6));
        int kcnt = (t == 0) ? NMETA_ : (kend - kbase);
        if (kcnt > 64) kcnt = 64;

        float s[8][4];
#pragma unroll
        for (int nf = 0; nf < 8; nf++)
#pragma unroll
            for (int e = 0; e < 4; e++) s[nf][e] = 0.f;

#pragma unroll
        for (int ks = 0; ks < 8; ks++) {
            const int kk = ks * 16;
#pragma unroll
            for (int nfp = 0; nfp < 4; nfp++) {
                u32 off = (u32)((nfp * 16 + (grp >> 1) * 8 + lrow) * AT_BKP
                                + kk + (grp & 1) * 8) * 2;
                u32 k2[4];
                ldsm_x4(k2, sK + off);
                mma16816(s[2 * nfp],     qf[ks], &k2[0]);
                mma16816(s[2 * nfp + 1], qf[ks], &k2[2]);
            }
        }

        float mx0 = -1e30f, mx1 = -1e30f;
        const bool fullv = (t > 0) && (kbase + 64 <= q0) && (kbase >= q0 - 448);
        if (fullv) {
#pragma unroll
            for (int nf = 0; nf < 8; nf++) {
#pragma unroll
                for (int e = 0; e < 4; e++) {
                    float v = s[nf][e] * scale2;
                    s[nf][e] = v;
                    if (e < 2) mx0 = fmaxf(mx0, v); else mx1 = fmaxf(mx1, v);
                }
            }
        } else {
#pragma unroll
            for (int nf = 0; nf < 8; nf++) {
#pragma unroll
                for (int e = 0; e < 4; e++) {
                    int col = nf * 8 + c0 + (e & 1);
                    int kpos = kbase + col;
                    int qp = (e < 2) ? qp0 : qp1;
                    bool ok = (col < kcnt) && (kpos <= qp) &&
                              ((kpos >= qp - (WINDOW_ - 1)) || (kpos < NMETA_));
                    float v = ok ? s[nf][e] * scale2 : -1e30f;
                    s[nf][e] = v;
                    if (e < 2) mx0 = fmaxf(mx0, v); else mx1 = fmaxf(mx1, v);
                }
            }
        }
        mx0 = fmaxf(mx0, __shfl_xor_sync(0xffffffffu, mx0, 1));
        mx0 = fmaxf(mx0, __shfl_xor_sync(0xffffffffu, mx0, 2));
        mx1 = fmaxf(mx1, __shfl_xor_sync(0xffffffffu, mx1, 1));
        mx1 = fmaxf(mx1, __shfl_xor_sync(0xffffffffu, mx1, 2));

        float mn0 = fmaxf(m0, mx0), mn1 = fmaxf(m1, mx1);
        float f0 = exp2f(m0 - mn0), f1 = exp2f(m1 - mn1);
        float rs0 = 0.f, rs1 = 0.f;
#pragma unroll
        for (int nf = 0; nf < 8; nf++) {
            float p0 = exp2f(s[nf][0] - mn0);
            float p1 = exp2f(s[nf][1] - mn0);
            float p2 = exp2f(s[nf][2] - mn1);
            float p3 = exp2f(s[nf][3] - mn1);
            s[nf][0] = p0; s[nf][1] = p1; s[nf][2] = p2; s[nf][3] = p3;
            rs0 += p0 + p1; rs1 += p2 + p3;
        }
        rs0 += __shfl_xor_sync(0xffffffffu, rs0, 1);
        rs0 += __shfl_xor_sync(0xffffffffu, rs0, 2);
        rs1 += __shfl_xor_sync(0xffffffffu, rs1, 1);
        rs1 += __shfl_xor_sync(0xffffffffu, rs1, 2);
        l0 = l0 * f0 + rs0; m0 = mn0;
        l1 = l1 * f1 + rs1; m1 = mn1;
#pragma unroll
        for (int nf = 0; nf < 16; nf++) {
            o[nf][0] *= f0; o[nf][1] *= f0;
            o[nf][2] *= f1; o[nf][3] *= f1;
        }

#pragma unroll
        for (int ks = 0; ks < 4; ks++) {
            u32 ph[4];
            ph[0] = packh2(s[2 * ks][0],     s[2 * ks][1]);
            ph[1] = packh2(s[2 * ks][2],     s[2 * ks][3]);
            ph[2] = packh2(s[2 * ks + 1][0], s[2 * ks + 1][1]);
            ph[3] = packh2(s[2 * ks + 1][2], s[2 * ks + 1][3]);
            const int kk = ks * 16;
#pragma unroll
            for (int nfp = 0; nfp < 8; nfp++) {
                u32 off = (u32)((kk + (grp & 1) * 8 + lrow) * AT_BKP
                                + nfp * 16 + (grp >> 1) * 8) * 2;
                u32 v2[4];
                ldsm_x4_t(v2, sV + off);
                mma16816(o[2 * nfp],     ph, &v2[0]);
                mma16816(o[2 * nfp + 1], ph, &v2[2]);
            }
        }
    }

    float i0 = 1.0f / l0, i1 = 1.0f / l1;
    const int row0 = q0 + w * 16 + g;
#pragma unroll
    for (int nf = 0; nf < 16; nf++) {
        int col = nf * 8 + c0;
        size_t a0 = ((size_t)(b * S_ + row0) * NH_ + h) * HD_ + col;
        size_t a1 = ((size_t)(b * S_ + row0 + 8) * NH_ + h) * HD_ + col;
        *(u32*)(y16 + a0) = packh2(o[nf][0] * i0, o[nf][1] * i0);
        *(u32*)(y16 + a1) = packh2(o[nf][2] * i1, o[nf][3] * i1);
    }
}

// ---------------------------------------------------------------------------
// Launch
// ---------------------------------------------------------------------------
extern "C" void kernel_launch(void* const* d_in, const int* in_sizes, int n_in,
                              void* d_out, int out_size)
{
    const float* x   = (const float*)d_in[0];
    const float* Wq  = (const float*)d_in[1];
    const float* bq  = (const float*)d_in[2];
    const float* Wkv = (const float*)d_in[3];
    const float* bkv = (const float*)d_in[4];
    const float* Wo  = (const float*)d_in[5];
    const float* bo  = (const float*)d_in[6];
    float* out = (float*)d_out;

    __half *x16, *q16, *kv16, *y16, *wqkvt, *wot;
    float *bqkv;
    float2* tab;
    cudaGetSymbolAddress((void**)&x16,   g_x16);
    cudaGetSymbolAddress((void**)&q16,   g_q16);
    cudaGetSymbolAddress((void**)&kv16,  g_kv16);
    cudaGetSymbolAddress((void**)&y16,   g_y16);
    cudaGetSymbolAddress((void**)&wqkvt, g_wqkvt);
    cudaGetSymbolAddress((void**)&wot,   g_wot);
    cudaGetSymbolAddress((void**)&bqkv,  g_bqkv);
    cudaGetSymbolAddress((void**)&tab,   g_ropetab);

    const int M = B_ * S_;
    const int n4 = (B_ * S_ * E_) / 4;

    convert_kernel<<<n4 / 256, 256>>>(x, x16, n4);
    prep_kernel<<<dim3(64, 64, 4), dim3(32, 8)>>>(
        Wq, Wkv, Wo, bq, bkv, wqkvt, wot, bqkv, tab);

    cudaFuncSetAttribute(mma_gemm_kernel, cudaFuncAttributeMaxDynamicSharedMemorySize,
                         GT_SMEM);
    cudaFuncSetAttribute(attn_mma_kernel, cudaFuncAttributeMaxDynamicSharedMemorySize,
                         ATT_SMEM);

    // fused [q | kv] = x @ [Wq | Wkv] + [bq | bkv]  (+RoPE, fp16 out)
    mma_gemm_kernel<<<dim3(QKVN_ / 128, M / 256), 256, GT_SMEM>>>(
        x16, wqkvt, bqkv, nullptr, q16, kv16, tab, M, QKVN_, E_, 1);

    // attention
    attn_mma_kernel<<<dim3(S_ / 64, B_ * NH_), 128, ATT_SMEM>>>(q16, kv16, y16);

    // out = y @ Wo + bo  (fp32 out)
    mma_gemm_kernel<<<dim3(E_ / 128, M / 256), 256, GT_SMEM>>>(
        y16, wot, bo, out, nullptr, nullptr, tab, M, E_, E_, 0);
}

// round 14
// speedup vs baseline: 1.1479x; 1.1479x over previous
#include <cuda_runtime.h>
#include <cuda_fp16.h>
#include <math.h>

typedef unsigned int u32;

// Problem constants
#define B_      2
#define S_      4096
#define E_      2048
#define NH_     16
#define HD_     128
#define NKV_    4
#define KVOUT_  1024
#define QKVN_   3072
#define WINDOW_ 512
#define NMETA_  16

// ---------------------------------------------------------------------------
// Scratch (device globals)
// ---------------------------------------------------------------------------
__device__ __half g_x16 [B_ * S_ * E_];
__device__ __half g_q16 [B_ * S_ * E_];
__device__ __half g_kv16[B_ * S_ * KVOUT_];
__device__ __half g_y16 [B_ * S_ * E_];
__device__ __half g_wqkvt[QKVN_ * E_];
__device__ __half g_wot [E_ * E_];
__device__ float  g_bqkv[QKVN_];
__device__ float2 g_ropetab[S_ * 64];

// ---------------------------------------------------------------------------
// Helpers
// ---------------------------------------------------------------------------
__device__ __forceinline__ u32 smem_u32(const void* p) {
    u32 a;
    asm("{ .reg .u64 t; cvta.to.shared.u64 t, %1; cvt.u32.u64 %0, t; }"
        : "=r"(a) : "l"(p));
    return a;
}

__device__ __forceinline__ void mma16816(float* d, const u32* a, const u32* b)
{
    asm volatile(
        "mma.sync.aligned.m16n8k16.row.col.f32.f16.f16.f32 "
        "{%0,%1,%2,%3}, {%4,%5,%6,%7}, {%8,%9}, {%0,%1,%2,%3};"
        : "+f"(d[0]), "+f"(d[1]), "+f"(d[2]), "+f"(d[3])
        : "r"(a[0]), "r"(a[1]), "r"(a[2]), "r"(a[3]), "r"(b[0]), "r"(b[1]));
}

__device__ __forceinline__ void ldsm_x4(u32* r, u32 addr)
{
    asm volatile("ldmatrix.sync.aligned.m8n8.x4.shared.b16 {%0,%1,%2,%3}, [%4];"
        : "=r"(r[0]), "=r"(r[1]), "=r"(r[2]), "=r"(r[3]) : "r"(addr));
}

__device__ __forceinline__ void ldsm_x4_t(u32* r, u32 addr)
{
    asm volatile("ldmatrix.sync.aligned.m8n8.x4.trans.shared.b16 {%0,%1,%2,%3}, [%4];"
        : "=r"(r[0]), "=r"(r[1]), "=r"(r[2]), "=r"(r[3]) : "r"(addr));
}

__device__ __forceinline__ u32 packh2(float x, float y)
{
    __half2 h = __floats2half2_rn(x, y);
    return *(u32*)&h;
}

#define CP_ASYNC16(dst, src) \
    asm volatile("cp.async.cg.shared.global [%0], [%1], 16;" :: "r"(dst), "l"(src))
#define CP_ASYNC16Z(dst, src, sz) \
    asm volatile("cp.async.cg.shared.global [%0], [%1], 16, %2;" \
                 :: "r"(dst), "l"(src), "r"(sz))
#define CP_COMMIT() asm volatile("cp.async.commit_group;")
#define CP_WAIT1()  asm volatile("cp.async.wait_group 1;")
#define CP_WAIT0()  asm volatile("cp.async.wait_group 0;")

// ---------------------------------------------------------------------------
// Unified prep: z=0..2 weight transposes, z=3 rope table + bias concat,
// z=4 x -> fp16 convert.
// ---------------------------------------------------------------------------
__global__ void prep_kernel(const float* __restrict__ x,
                            const float* __restrict__ Wq,
                            const float* __restrict__ Wkv,
                            const float* __restrict__ Wo,
                            const float* __restrict__ bq,
                            const float* __restrict__ bkv,
                            __half* __restrict__ x16,
                            __half* __restrict__ wqkvt,
                            __half* __restrict__ wot,
                            float* __restrict__ bqkv,
                            float2* __restrict__ tab)
{
    int z = blockIdx.z;
    if (z < 3) {
        const float* W;
        __half* T;
        int N;
        if (z == 0)      { W = Wq;  T = wqkvt;                   N = E_; }
        else if (z == 1) { W = Wkv; T = wqkvt + (size_t)E_ * E_; N = KVOUT_; }
        else             { W = Wo;  T = wot;                     N = E_; }
        const int K = E_;
        __shared__ float t[32][33];
        int n0 = blockIdx.x * 32, k0 = blockIdx.y * 32;
        if (n0 >= N) return;
        for (int i = threadIdx.y; i < 32; i += 8)
            t[i][threadIdx.x] = W[(size_t)(k0 + i) * N + n0 + threadIdx.x];
        __syncthreads();
        for (int i = threadIdx.y; i < 32; i += 8)
            T[(size_t)(n0 + i) * K + k0 + threadIdx.x] =
                __float2half_rn(t[threadIdx.x][i]);
    } else if (z == 3) {
        int t = (blockIdx.y * gridDim.x + blockIdx.x) * 256
                + threadIdx.y * 32 + threadIdx.x;
        if (t < S_ * 64) {
            int pos = t >> 6, i = t & 63;
            float inv = (float)exp(-(double)i * (9.210340371976184 / 64.0));
            float ang = (float)pos * inv;
            tab[t] = make_float2(cosf(ang), sinf(ang));
        } else {
            int u = t - S_ * 64;
            if (u < E_) bqkv[u] = bq[u];
            else if (u < QKVN_) bqkv[u] = bkv[u - E_];
        }
    } else {
        // x convert: 64*64*256 threads, 4 float4 each = 4M float4
        int base = (blockIdx.y * gridDim.x + blockIdx.x) * 256
                   + threadIdx.y * 32 + threadIdx.x;
        u32* O = (u32*)x16;
#pragma unroll
        for (int k = 0; k < 4; k++) {
            int i = base + k * (64 * 64 * 256);
            float4 v = ((const float4*)x)[i];
            O[i * 2]     = packh2(v.x, v.y);
            O[i * 2 + 1] = packh2(v.z, v.w);
        }
    }
}

// ---------------------------------------------------------------------------
// mma.sync fp16 GEMM (R12 config). Block 128x128x64, 4 warps (2m x 2n) of
// 64x64 tiles, cp.async 3-stage, one __syncthreads per chunk, 2 CTAs/SM.
// mode 0: fp32 out. mode 1: fused qkv out (rope cols < 2560).
// ---------------------------------------------------------------------------
#define BKP       72
#define TILE_ELEM (128 * BKP)
#define STAGE_ELEM (2 * TILE_ELEM)
#define GT_SMEM   (3 * STAGE_ELEM * 2)

__global__ __launch_bounds__(128, 2) void mma_gemm_kernel(
    const __half* __restrict__ A, const __half* __restrict__ Bm,
    const float* __restrict__ bias, float* __restrict__ Cf,
    __half* __restrict__ Cq, __half* __restrict__ Ckv,
    const float2* __restrict__ tab, int M, int N, int K, int mode)
{
    extern __shared__ __half sm[];
    const u32 sbase = smem_u32(sm);
    const int tid = threadIdx.x;
    const int wid = tid >> 5, lane = tid & 31;
    const int wm = wid & 1, wn = wid >> 1;
    const int m0 = blockIdx.y * 128;
    const int n0 = blockIdx.x * 128;
    const int g  = lane >> 2;
    const int c0 = (lane & 3) * 2;
    const int lrow = lane & 7, grp = lane >> 3;

    auto load_stage = [&](int c, int stage) {
        const int k0 = c * 64;
        const u32 sb = sbase + stage * STAGE_ELEM * 2;
#pragma unroll
        for (int i = 0; i < 8; i++) {
            int idx = tid + i * 128;
            int row = idx >> 3, q8 = idx & 7;
            u32 soff = (u32)(row * BKP + q8 * 8) * 2;
            size_t ga = (size_t)(m0 + row) * K + k0 + q8 * 8;
            size_t gb = (size_t)(n0 + row) * K + k0 + q8 * 8;
            CP_ASYNC16(sb + soff,                 (const char*)(A + ga));
            CP_ASYNC16(sb + TILE_ELEM * 2 + soff, (const char*)(Bm + gb));
        }
    };

    float acc[4][8][4];
#pragma unroll
    for (int i = 0; i < 4; i++)
#pragma unroll
        for (int j = 0; j < 8; j++)
#pragma unroll
            for (int e = 0; e < 4; e++) acc[i][j][e] = 0.f;

    const int nc = K >> 6;
    load_stage(0, 0); CP_COMMIT();
    load_stage(1, 1); CP_COMMIT();

    for (int c = 0; c < nc; c++) {
        if (c + 1 < nc) CP_WAIT1(); else CP_WAIT0();
        __syncthreads();
        if (c + 2 < nc) {
            load_stage(c + 2, (c + 2) % 3);
            CP_COMMIT();
        }

        const u32 st = sbase + (u32)((c % 3) * STAGE_ELEM) * 2;
        const u32 sA = st;
        const u32 sB = st + TILE_ELEM * 2;

#pragma unroll
        for (int kh = 0; kh < 4; kh++) {
            const int kk = kh * 16;
            u32 bfr[8][2];
#pragma unroll
            for (int nfp = 0; nfp < 4; nfp++) {
                u32 off = (u32)((wn * 64 + nfp * 16 + (grp >> 1) * 8 + lrow) * BKP
                                + kk + (grp & 1) * 8) * 2;
                ldsm_x4(&bfr[nfp * 2][0], sB + off);
            }
#pragma unroll
            for (int mf = 0; mf < 4; mf++) {
                u32 offa = (u32)((wm * 64 + mf * 16 + (grp & 1) * 8 + lrow) * BKP
                                 + kk + (grp >> 1) * 8) * 2;
                u32 a[4];
                ldsm_x4(a, sA + offa);
#pragma unroll
                for (int nf = 0; nf < 8; nf++)
                    mma16816(acc[mf][nf], a, bfr[nf]);
            }
        }
    }

    // Epilogue
#pragma unroll
    for (int mf = 0; mf < 4; mf++) {
        int row0 = m0 + wm * 64 + mf * 16 + g;
        int pos0 = row0 & (S_ - 1);
        int pos1 = (row0 + 8) & (S_ - 1);
#pragma unroll
        for (int nf = 0; nf < 8; nf++) {
            int col = n0 + wn * 64 + nf * 8 + c0;
            float b0 = bias[col], b1 = bias[col + 1];
            float v0 = acc[mf][nf][0] + b0, v1 = acc[mf][nf][1] + b1;
            float v2 = acc[mf][nf][2] + b0, v3 = acc[mf][nf][3] + b1;
            if (mode == 0) {
                *(float2*)(Cf + (size_t)row0 * N + col)       = make_float2(v0, v1);
                *(float2*)(Cf + (size_t)(row0 + 8) * N + col) = make_float2(v2, v3);
            } else {
                bool do_rope = (col < 2560);
                if (do_rope) {
                    int ti = (col & 127) >> 1;
                    float2 cs0 = tab[pos0 * 64 + ti];
                    float2 cs1 = tab[pos1 * 64 + ti];
                    float t0 = v0, t1 = v1;
                    v0 = t0 * cs0.x - t1 * cs0.y;
                    v1 = t1 * cs0.x + t0 * cs0.y;
                    float t2 = v2, t3 = v3;
                    v2 = t2 * cs1.x - t3 * cs1.y;
                    v3 = t3 * cs1.x + t2 * cs1.y;
                }
                if (col < E_) {
                    *(u32*)(Cq + (size_t)row0 * E_ + col)       = packh2(v0, v1);
                    *(u32*)(Cq + (size_t)(row0 + 8) * E_ + col) = packh2(v2, v3);
                } else {
                    int c2 = col - E_;
                    *(u32*)(Ckv + (size_t)row0 * KVOUT_ + c2)       = packh2(v0, v1);
                    *(u32*)(Ckv + (size_t)(row0 + 8) * KVOUT_ + c2) = packh2(v2, v3);
                }
            }
        }
    }
}

// ---------------------------------------------------------------------------
// Attention: mma.sync fp16, 3-stage cp.async K/V pipeline, mask hoisting,
// exp2-domain softmax, meta-tile fast path (16-key tile does 1/4 the MMAs).
// ---------------------------------------------------------------------------
#define AT_BKP   136
#define AT_TILE  (64 * AT_BKP)
#define AT_STAGE (2 * AT_TILE)
#define ATT_SMEM (3 * AT_STAGE * 2)

__global__ __launch_bounds__(128, 2) void attn_mma_kernel(
    const __half* __restrict__ q16, const __half* __restrict__ kv16,
    __half* __restrict__ y16)
{
    extern __shared__ __half sm[];
    const u32 smb = smem_u32(sm);
    const int tid = threadIdx.x;
    const int w = tid >> 5, lane = tid & 31;
    const int g = lane >> 2, c0 = (lane & 3) * 2;
    const int lrow = lane & 7, grp = lane >> 3;
    const int bhp = blockIdx.y;
    const int b = bhp >> 4, h = bhp & 15;
    const int kv_h = h >> 2;
    const int q0 = blockIdx.x << 6;
    int ls = q0 - WINDOW_ + 1; if (ls < NMETA_) ls = NMETA_;
    const int kend = q0 + 64;
    const float scale2 = 0.088388347648318447f * 1.4426950408889634f;

#pragma unroll
    for (int it = 0; it < 8; it++) {
        int fi = tid + it * 128;
        int r = fi >> 4, q8 = fi & 15;
        size_t ga = ((size_t)(b * S_ + q0 + r) * NH_ + h) * HD_ + q8 * 8;
        CP_ASYNC16(smb + (u32)(r * AT_BKP + q8 * 8) * 2, (const char*)(q16 + ga));
    }
    CP_COMMIT(); CP_WAIT0();
    __syncthreads();

    u32 qf[8][4];
#pragma unroll
    for (int ks = 0; ks < 8; ks++) {
        u32 off = (u32)((w * 16 + (grp & 1) * 8 + lrow) * AT_BKP
                        + ks * 16 + (grp >> 1) * 8) * 2;
        ldsm_x4(qf[ks], smb + off);
    }
    __syncthreads();

    auto load_tile = [&](int t, int stage) {
        int kb = (t == 0) ? 0 : (ls + ((t - 1) << 6));
        int kc = (t == 0) ? NMETA_ : (kend - kb);
        if (kc > 64) kc = 64;
        u32 sK = smb + (u32)(stage * AT_STAGE) * 2;
        u32 sV = sK + AT_TILE * 2;
#pragma unroll
        for (int it = 0; it < 8; it++) {
            int fi = tid + it * 128;
            int r = fi >> 4, q8 = fi & 15;
            int sz = (r < kc) ? 16 : 0;
            int rr = (r < kc) ? r : 0;
            size_t base = (size_t)(b * S_ + kb + rr) * 1024 + kv_h * 128 + q8 * 8;
            u32 off = (u32)(r * AT_BKP + q8 * 8) * 2;
            CP_ASYNC16Z(sK + off, (const char*)(kv16 + base), sz);
            CP_ASYNC16Z(sV + off, (const char*)(kv16 + base + 512), sz);
        }
    };

    float m0 = -1e30f, m1 = -1e30f, l0 = 0.f, l1 = 0.f;
    float o[16][4];
#pragma unroll
    for (int i = 0; i < 16; i++)
#pragma unroll
        for (int e = 0; e < 4; e++) o[i][e] = 0.f;

    const int qp0 = q0 + w * 16 + g;
    const int qp1 = qp0 + 8;
    const int nT = 1 + ((kend - ls + 63) >> 6);

    load_tile(0, 0); CP_COMMIT();
    load_tile(1, 1); CP_COMMIT();

    for (int t = 0; t < nT; t++) {
        if (t + 1 < nT) CP_WAIT1(); else CP_WAIT0();
        __syncthreads();
        if (t + 2 < nT) {
            load_tile(t + 2, (t + 2) % 3);
            CP_COMMIT();
        }

        const u32 sK = smb + (u32)((t % 3) * AT_STAGE) * 2;
        const u32 sV = sK + AT_TILE * 2;

        if (t == 0) {
            // ---- Meta tile fast path: only 16 keys (cols 0..15, ks chunk 0) ----
            float s[2][4];
#pragma unroll
            for (int nf = 0; nf < 2; nf++)
#pragma unroll
                for (int e = 0; e < 4; e++) s[nf][e] = 0.f;

#pragma unroll
            for (int ks = 0; ks < 8; ks++) {
                const int kk = ks * 16;
                u32 off = (u32)(((grp >> 1) * 8 + lrow) * AT_BKP
                                + kk + (grp & 1) * 8) * 2;
                u32 k2[4];
                ldsm_x4(k2, sK + off);
                mma16816(s[0], qf[ks], &k2[0]);
                mma16816(s[1], qf[ks], &k2[2]);
            }

            float mx0 = -1e30f, mx1 = -1e30f;
#pragma unroll
            for (int nf = 0; nf < 2; nf++) {
#pragma unroll
                for (int e = 0; e < 4; e++) {
                    int col = nf * 8 + c0 + (e & 1);
                    int qp = (e < 2) ? qp0 : qp1;
                    bool ok = (col <= qp);   // meta keys always in meta set
                    float v = ok ? s[nf][e] * scale2 : -1e30f;
                    s[nf][e] = v;
                    if (e < 2) mx0 = fmaxf(mx0, v); else mx1 = fmaxf(mx1, v);
                }
            }
            mx0 = fmaxf(mx0, __shfl_xor_sync(0xffffffffu, mx0, 1));
            mx0 = fmaxf(mx0, __shfl_xor_sync(0xffffffffu, mx0, 2));
            mx1 = fmaxf(mx1, __shfl_xor_sync(0xffffffffu, mx1, 1));
            mx1 = fmaxf(mx1, __shfl_xor_sync(0xffffffffu, mx1, 2));

            float mn0 = fmaxf(m0, mx0), mn1 = fmaxf(m1, mx1);
            float rs0 = 0.f, rs1 = 0.f;
#pragma unroll
            for (int nf = 0; nf < 2; nf++) {
                float p0 = exp2f(s[nf][0] - mn0);
                float p1 = exp2f(s[nf][1] - mn0);
                float p2 = exp2f(s[nf][2] - mn1);
                float p3 = exp2f(s[nf][3] - mn1);
                s[nf][0] = p0; s[nf][1] = p1; s[nf][2] = p2; s[nf][3] = p3;
                rs0 += p0 + p1; rs1 += p2 + p3;
            }
            rs0 += __shfl_xor_sync(0xffffffffu, rs0, 1);
            rs0 += __shfl_xor_sync(0xffffffffu, rs0, 2);
            rs1 += __shfl_xor_sync(0xffffffffu, rs1, 1);
            rs1 += __shfl_xor_sync(0xffffffffu, rs1, 2);
            // first tile: l,m start empty
            l0 = rs0; m0 = mn0;
            l1 = rs1; m1 = mn1;

            // PV on ks chunk 0 only (V rows >= 16 are zero anyway)
            u32 ph[4];
            ph[0] = packh2(s[0][0], s[0][1]);
            ph[1] = packh2(s[0][2], s[0][3]);
            ph[2] = packh2(s[1][0], s[1][1]);
            ph[3] = packh2(s[1][2], s[1][3]);
#pragma unroll
            for (int nfp = 0; nfp < 8; nfp++) {
                u32 off = (u32)(((grp & 1) * 8 + lrow) * AT_BKP
                                + nfp * 16 + (grp >> 1) * 8) * 2;
                u32 v2[4];
                ldsm_x4_t(v2, sV + off);
                mma16816(o[2 * nfp],     ph, &v2[0]);
                mma16816(o[2 * nfp + 1], ph, &v2[2]);
            }
            continue;
        }

        const int kbase = ls + ((t - 1) << 6);
        int kcnt = kend - kbase;
        if (kcnt > 64) kcnt = 64;

        // --- QK^T single pass ---
        float s[8][4];
#pragma unroll
        for (int nf = 0; nf < 8; nf++)
#pragma unroll
            for (int e = 0; e < 4; e++) s[nf][e] = 0.f;

#pragma unroll
        for (int ks = 0; ks < 8; ks++) {
            const int kk = ks * 16;
#pragma unroll
            for (int nfp = 0; nfp < 4; nfp++) {
                u32 off = (u32)((nfp * 16 + (grp >> 1) * 8 + lrow) * AT_BKP
                                + kk + (grp & 1) * 8) * 2;
                u32 k2[4];
                ldsm_x4(k2, sK + off);
                mma16816(s[2 * nfp],     qf[ks], &k2[0]);
                mma16816(s[2 * nfp + 1], qf[ks], &k2[2]);
            }
        }

        float mx0 = -1e30f, mx1 = -1e30f;
        const bool fullv = (kbase + 64 <= q0) && (kbase >= q0 - 448);
        if (fullv) {
#pragma unroll
            for (int nf = 0; nf < 8; nf++) {
#pragma unroll
                for (int e = 0; e < 4; e++) {
                    float v = s[nf][e] * scale2;
                    s[nf][e] = v;
                    if (e < 2) mx0 = fmaxf(mx0, v); else mx1 = fmaxf(mx1, v);
                }
            }
        } else {
#pragma unroll
            for (int nf = 0; nf < 8; nf++) {
#pragma unroll
                for (int e = 0; e < 4; e++) {
                    int col = nf * 8 + c0 + (e & 1);
                    int kpos = kbase + col;
                    int qp = (e < 2) ? qp0 : qp1;
                    bool ok = (col < kcnt) && (kpos <= qp) &&
                              ((kpos >= qp - (WINDOW_ - 1)) || (kpos < NMETA_));
                    float v = ok ? s[nf][e] * scale2 : -1e30f;
                    s[nf][e] = v;
                    if (e < 2) mx0 = fmaxf(mx0, v); else mx1 = fmaxf(mx1, v);
                }
            }
        }
        mx0 = fmaxf(mx0, __shfl_xor_sync(0xffffffffu, mx0, 1));
        mx0 = fmaxf(mx0, __shfl_xor_sync(0xffffffffu, mx0, 2));
        mx1 = fmaxf(mx1, __shfl_xor_sync(0xffffffffu, mx1, 1));
        mx1 = fmaxf(mx1, __shfl_xor_sync(0xffffffffu, mx1, 2));

        float mn0 = fmaxf(m0, mx0), mn1 = fmaxf(m1, mx1);
        float f0 = exp2f(m0 - mn0), f1 = exp2f(m1 - mn1);
        float rs0 = 0.f, rs1 = 0.f;
#pragma unroll
        for (int nf = 0; nf < 8; nf++) {
            float p0 = exp2f(s[nf][0] - mn0);
            float p1 = exp2f(s[nf][1] - mn0);
            float p2 = exp2f(s[nf][2] - mn1);
            float p3 = exp2f(s[nf][3] - mn1);
            s[nf][0] = p0; s[nf][1] = p1; s[nf][2] = p2; s[nf][3] = p3;
            rs0 += p0 + p1; rs1 += p2 + p3;
        }
        rs0 += __shfl_xor_sync(0xffffffffu, rs0, 1);
        rs0 += __shfl_xor_sync(0xffffffffu, rs0, 2);
        rs1 += __shfl_xor_sync(0xffffffffu, rs1, 1);
        rs1 += __shfl_xor_sync(0xffffffffu, rs1, 2);
        l0 = l0 * f0 + rs0; m0 = mn0;
        l1 = l1 * f1 + rs1; m1 = mn1;
#pragma unroll
        for (int nf = 0; nf < 16; nf++) {
            o[nf][0] *= f0; o[nf][1] *= f0;
            o[nf][2] *= f1; o[nf][3] *= f1;
        }

#pragma unroll
        for (int ks = 0; ks < 4; ks++) {
            u32 ph[4];
            ph[0] = packh2(s[2 * ks][0],     s[2 * ks][1]);
            ph[1] = packh2(s[2 * ks][2],     s[2 * ks][3]);
            ph[2] = packh2(s[2 * ks + 1][0], s[2 * ks + 1][1]);
            ph[3] = packh2(s[2 * ks + 1][2], s[2 * ks + 1][3]);
            const int kk = ks * 16;
#pragma unroll
            for (int nfp = 0; nfp < 8; nfp++) {
                u32 off = (u32)((kk + (grp & 1) * 8 + lrow) * AT_BKP
                                + nfp * 16 + (grp >> 1) * 8) * 2;
                u32 v2[4];
                ldsm_x4_t(v2, sV + off);
                mma16816(o[2 * nfp],     ph, &v2[0]);
                mma16816(o[2 * nfp + 1], ph, &v2[2]);
            }
        }
    }

    float i0 = 1.0f / l0, i1 = 1.0f / l1;
    const int row0 = q0 + w * 16 + g;
#pragma unroll
    for (int nf = 0; nf < 16; nf++) {
        int col = nf * 8 + c0;
        size_t a0 = ((size_t)(b * S_ + row0) * NH_ + h) * HD_ + col;
        size_t a1 = ((size_t)(b * S_ + row0 + 8) * NH_ + h) * HD_ + col;
        *(u32*)(y16 + a0) = packh2(o[nf][0] * i0, o[nf][1] * i0);
        *(u32*)(y16 + a1) = packh2(o[nf][2] * i1, o[nf][3] * i1);
    }
}

// ---------------------------------------------------------------------------
// Launch
// ---------------------------------------------------------------------------
extern "C" void kernel_launch(void* const* d_in, const int* in_sizes, int n_in,
                              void* d_out, int out_size)
{
    const float* x   = (const float*)d_in[0];
    const float* Wq  = (const float*)d_in[1];
    const float* bq  = (const float*)d_in[2];
    const float* Wkv = (const float*)d_in[3];
    const float* bkv = (const float*)d_in[4];
    const float* Wo  = (const float*)d_in[5];
    const float* bo  = (const float*)d_in[6];
    float* out = (float*)d_out;

    __half *x16, *q16, *kv16, *y16, *wqkvt, *wot;
    float *bqkv;
    float2* tab;
    cudaGetSymbolAddress((void**)&x16,   g_x16);
    cudaGetSymbolAddress((void**)&q16,   g_q16);
    cudaGetSymbolAddress((void**)&kv16,  g_kv16);
    cudaGetSymbolAddress((void**)&y16,   g_y16);
    cudaGetSymbolAddress((void**)&wqkvt, g_wqkvt);
    cudaGetSymbolAddress((void**)&wot,   g_wot);
    cudaGetSymbolAddress((void**)&bqkv,  g_bqkv);
    cudaGetSymbolAddress((void**)&tab,   g_ropetab);

    const int M = B_ * S_;

    prep_kernel<<<dim3(64, 64, 5), dim3(32, 8)>>>(
        x, Wq, Wkv, Wo, bq, bkv, x16, wqkvt, wot, bqkv, tab);

    cudaFuncSetAttribute(mma_gemm_kernel, cudaFuncAttributeMaxDynamicSharedMemorySize,
                         GT_SMEM);
    cudaFuncSetAttribute(attn_mma_kernel, cudaFuncAttributeMaxDynamicSharedMemorySize,
                         ATT_SMEM);

    // fused [q | kv] = x @ [Wq | Wkv] + [bq | bkv]  (+RoPE, fp16 out)
    mma_gemm_kernel<<<dim3(QKVN_ / 128, M / 128), 128, GT_SMEM>>>(
        x16, wqkvt, bqkv, nullptr, q16, kv16, tab, M, QKVN_, E_, 1);

    // attention
    attn_mma_kernel<<<dim3(S_ / 64, B_ * NH_), 128, ATT_SMEM>>>(q16, kv16, y16);

    // out = y @ Wo + bo  (fp32 out)
    mma_gemm_kernel<<<dim3(E_ / 128, M / 128), 128, GT_SMEM>>>(
        y16, wot, bo, out, nullptr, nullptr, tab, M, E_, E_, 0);
}

// round 15
// speedup vs baseline: 1.2146x; 1.0581x over previous
#include <cuda_runtime.h>
#include <cuda_fp16.h>
#include <math.h>

typedef unsigned int u32;

// Problem constants
#define B_      2
#define S_      4096
#define E_      2048
#define NH_     16
#define HD_     128
#define NKV_    4
#define KVOUT_  1024
#define QKVN_   3072
#define WINDOW_ 512
#define NMETA_  16

// ---------------------------------------------------------------------------
// Scratch (device globals)
// ---------------------------------------------------------------------------
__device__ __half g_x16 [B_ * S_ * E_];
__device__ __half g_q16 [B_ * S_ * E_];
__device__ __half g_kv16[B_ * S_ * KVOUT_];
__device__ __half g_y16 [B_ * S_ * E_];
__device__ __half g_wqkvt[QKVN_ * E_];
__device__ __half g_wot [E_ * E_];
__device__ float  g_bqkv[QKVN_];
__device__ float2 g_ropetab[S_ * 64];

// ---------------------------------------------------------------------------
// Helpers
// ---------------------------------------------------------------------------
__device__ __forceinline__ u32 smem_u32(const void* p) {
    u32 a;
    asm("{ .reg .u64 t; cvta.to.shared.u64 t, %1; cvt.u32.u64 %0, t; }"
        : "=r"(a) : "l"(p));
    return a;
}

__device__ __forceinline__ void mma16816(float* d, const u32* a, const u32* b)
{
    asm volatile(
        "mma.sync.aligned.m16n8k16.row.col.f32.f16.f16.f32 "
        "{%0,%1,%2,%3}, {%4,%5,%6,%7}, {%8,%9}, {%0,%1,%2,%3};"
        : "+f"(d[0]), "+f"(d[1]), "+f"(d[2]), "+f"(d[3])
        : "r"(a[0]), "r"(a[1]), "r"(a[2]), "r"(a[3]), "r"(b[0]), "r"(b[1]));
}

__device__ __forceinline__ void ldsm_x4(u32* r, u32 addr)
{
    asm volatile("ldmatrix.sync.aligned.m8n8.x4.shared.b16 {%0,%1,%2,%3}, [%4];"
        : "=r"(r[0]), "=r"(r[1]), "=r"(r[2]), "=r"(r[3]) : "r"(addr));
}

__device__ __forceinline__ void ldsm_x4_t(u32* r, u32 addr)
{
    asm volatile("ldmatrix.sync.aligned.m8n8.x4.trans.shared.b16 {%0,%1,%2,%3}, [%4];"
        : "=r"(r[0]), "=r"(r[1]), "=r"(r[2]), "=r"(r[3]) : "r"(addr));
}

__device__ __forceinline__ u32 packh2(float x, float y)
{
    __half2 h = __floats2half2_rn(x, y);
    return *(u32*)&h;
}

#define CP_ASYNC16(dst, src) \
    asm volatile("cp.async.cg.shared.global [%0], [%1], 16;" :: "r"(dst), "l"(src))
#define CP_ASYNC16Z(dst, src, sz) \
    asm volatile("cp.async.cg.shared.global [%0], [%1], 16, %2;" \
                 :: "r"(dst), "l"(src), "r"(sz))
#define CP_COMMIT() asm volatile("cp.async.commit_group;")
#define CP_WAIT1()  asm volatile("cp.async.wait_group 1;")
#define CP_WAIT0()  asm volatile("cp.async.wait_group 0;")

// ---------------------------------------------------------------------------
// Unified prep: z=0..2 weight transposes, z=3 rope table + bias concat,
// z=4 x -> fp16 convert.
// ---------------------------------------------------------------------------
__global__ void prep_kernel(const float* __restrict__ x,
                            const float* __restrict__ Wq,
                            const float* __restrict__ Wkv,
                            const float* __restrict__ Wo,
                            const float* __restrict__ bq,
                            const float* __restrict__ bkv,
                            __half* __restrict__ x16,
                            __half* __restrict__ wqkvt,
                            __half* __restrict__ wot,
                            float* __restrict__ bqkv,
                            float2* __restrict__ tab)
{
    int z = blockIdx.z;
    if (z < 3) {
        const float* W;
        __half* T;
        int N;
        if (z == 0)      { W = Wq;  T = wqkvt;                   N = E_; }
        else if (z == 1) { W = Wkv; T = wqkvt + (size_t)E_ * E_; N = KVOUT_; }
        else             { W = Wo;  T = wot;                     N = E_; }
        const int K = E_;
        __shared__ float t[32][33];
        int n0 = blockIdx.x * 32, k0 = blockIdx.y * 32;
        if (n0 >= N) return;
        for (int i = threadIdx.y; i < 32; i += 8)
            t[i][threadIdx.x] = W[(size_t)(k0 + i) * N + n0 + threadIdx.x];
        __syncthreads();
        for (int i = threadIdx.y; i < 32; i += 8)
            T[(size_t)(n0 + i) * K + k0 + threadIdx.x] =
                __float2half_rn(t[threadIdx.x][i]);
    } else if (z == 3) {
        int t = (blockIdx.y * gridDim.x + blockIdx.x) * 256
                + threadIdx.y * 32 + threadIdx.x;
        if (t < S_ * 64) {
            int pos = t >> 6, i = t & 63;
            float inv = (float)exp(-(double)i * (9.210340371976184 / 64.0));
            float ang = (float)pos * inv;
            tab[t] = make_float2(cosf(ang), sinf(ang));
        } else {
            int u = t - S_ * 64;
            if (u < E_) bqkv[u] = bq[u];
            else if (u < QKVN_) bqkv[u] = bkv[u - E_];
        }
    } else {
        int base = (blockIdx.y * gridDim.x + blockIdx.x) * 256
                   + threadIdx.y * 32 + threadIdx.x;
        u32* O = (u32*)x16;
#pragma unroll
        for (int k = 0; k < 4; k++) {
            int i = base + k * (64 * 64 * 256);
            float4 v = ((const float4*)x)[i];
            O[i * 2]     = packh2(v.x, v.y);
            O[i * 2 + 1] = packh2(v.z, v.w);
        }
    }
}

// ---------------------------------------------------------------------------
// mma.sync fp16 GEMM (R14 config). Block 128x128x64, 4 warps (2m x 2n),
// cp.async 3-stage, 2 CTAs/SM. Pointers are PRE-OFFSET per batch; M = 4096.
// mode 0: fp32 out. mode 1: fused qkv out (rope cols < 2560).
// ---------------------------------------------------------------------------
#define BKP       72
#define TILE_ELEM (128 * BKP)
#define STAGE_ELEM (2 * TILE_ELEM)
#define GT_SMEM   (3 * STAGE_ELEM * 2)

__global__ __launch_bounds__(128, 2) void mma_gemm_kernel(
    const __half* __restrict__ A, const __half* __restrict__ Bm,
    const float* __restrict__ bias, float* __restrict__ Cf,
    __half* __restrict__ Cq, __half* __restrict__ Ckv,
    const float2* __restrict__ tab, int M, int N, int K, int mode)
{
    extern __shared__ __half sm[];
    const u32 sbase = smem_u32(sm);
    const int tid = threadIdx.x;
    const int wid = tid >> 5, lane = tid & 31;
    const int wm = wid & 1, wn = wid >> 1;
    const int m0 = blockIdx.y * 128;
    const int n0 = blockIdx.x * 128;
    const int g  = lane >> 2;
    const int c0 = (lane & 3) * 2;
    const int lrow = lane & 7, grp = lane >> 3;

    auto load_stage = [&](int c, int stage) {
        const int k0 = c * 64;
        const u32 sb = sbase + stage * STAGE_ELEM * 2;
#pragma unroll
        for (int i = 0; i < 8; i++) {
            int idx = tid + i * 128;
            int row = idx >> 3, q8 = idx & 7;
            u32 soff = (u32)(row * BKP + q8 * 8) * 2;
            size_t ga = (size_t)(m0 + row) * K + k0 + q8 * 8;
            size_t gb = (size_t)(n0 + row) * K + k0 + q8 * 8;
            CP_ASYNC16(sb + soff,                 (const char*)(A + ga));
            CP_ASYNC16(sb + TILE_ELEM * 2 + soff, (const char*)(Bm + gb));
        }
    };

    float acc[4][8][4];
#pragma unroll
    for (int i = 0; i < 4; i++)
#pragma unroll
        for (int j = 0; j < 8; j++)
#pragma unroll
            for (int e = 0; e < 4; e++) acc[i][j][e] = 0.f;

    const int nc = K >> 6;
    load_stage(0, 0); CP_COMMIT();
    load_stage(1, 1); CP_COMMIT();

    for (int c = 0; c < nc; c++) {
        if (c + 1 < nc) CP_WAIT1(); else CP_WAIT0();
        __syncthreads();
        if (c + 2 < nc) {
            load_stage(c + 2, (c + 2) % 3);
            CP_COMMIT();
        }

        const u32 st = sbase + (u32)((c % 3) * STAGE_ELEM) * 2;
        const u32 sA = st;
        const u32 sB = st + TILE_ELEM * 2;

#pragma unroll
        for (int kh = 0; kh < 4; kh++) {
            const int kk = kh * 16;
            u32 bfr[8][2];
#pragma unroll
            for (int nfp = 0; nfp < 4; nfp++) {
                u32 off = (u32)((wn * 64 + nfp * 16 + (grp >> 1) * 8 + lrow) * BKP
                                + kk + (grp & 1) * 8) * 2;
                ldsm_x4(&bfr[nfp * 2][0], sB + off);
            }
#pragma unroll
            for (int mf = 0; mf < 4; mf++) {
                u32 offa = (u32)((wm * 64 + mf * 16 + (grp & 1) * 8 + lrow) * BKP
                                 + kk + (grp >> 1) * 8) * 2;
                u32 a[4];
                ldsm_x4(a, sA + offa);
#pragma unroll
                for (int nf = 0; nf < 8; nf++)
                    mma16816(acc[mf][nf], a, bfr[nf]);
            }
        }
    }

    // Epilogue
#pragma unroll
    for (int mf = 0; mf < 4; mf++) {
        int row0 = m0 + wm * 64 + mf * 16 + g;
        int pos0 = row0 & (S_ - 1);
        int pos1 = (row0 + 8) & (S_ - 1);
#pragma unroll
        for (int nf = 0; nf < 8; nf++) {
            int col = n0 + wn * 64 + nf * 8 + c0;
            float b0 = bias[col], b1 = bias[col + 1];
            float v0 = acc[mf][nf][0] + b0, v1 = acc[mf][nf][1] + b1;
            float v2 = acc[mf][nf][2] + b0, v3 = acc[mf][nf][3] + b1;
            if (mode == 0) {
                *(float2*)(Cf + (size_t)row0 * N + col)       = make_float2(v0, v1);
                *(float2*)(Cf + (size_t)(row0 + 8) * N + col) = make_float2(v2, v3);
            } else {
                bool do_rope = (col < 2560);
                if (do_rope) {
                    int ti = (col & 127) >> 1;
                    float2 cs0 = tab[pos0 * 64 + ti];
                    float2 cs1 = tab[pos1 * 64 + ti];
                    float t0 = v0, t1 = v1;
                    v0 = t0 * cs0.x - t1 * cs0.y;
                    v1 = t1 * cs0.x + t0 * cs0.y;
                    float t2 = v2, t3 = v3;
                    v2 = t2 * cs1.x - t3 * cs1.y;
                    v3 = t3 * cs1.x + t2 * cs1.y;
                }
                if (col < E_) {
                    *(u32*)(Cq + (size_t)row0 * E_ + col)       = packh2(v0, v1);
                    *(u32*)(Cq + (size_t)(row0 + 8) * E_ + col) = packh2(v2, v3);
                } else {
                    int c2 = col - E_;
                    *(u32*)(Ckv + (size_t)row0 * KVOUT_ + c2)       = packh2(v0, v1);
                    *(u32*)(Ckv + (size_t)(row0 + 8) * KVOUT_ + c2) = packh2(v2, v3);
                }
            }
        }
    }
}

// ---------------------------------------------------------------------------
// Attention (R14, per-batch pointers). grid = (S/64, NH).
// ---------------------------------------------------------------------------
#define AT_BKP   136
#define AT_TILE  (64 * AT_BKP)
#define AT_STAGE (2 * AT_TILE)
#define ATT_SMEM (3 * AT_STAGE * 2)

__global__ __launch_bounds__(128, 2) void attn_mma_kernel(
    const __half* __restrict__ q16, const __half* __restrict__ kv16,
    __half* __restrict__ y16)
{
    extern __shared__ __half sm[];
    const u32 smb = smem_u32(sm);
    const int tid = threadIdx.x;
    const int w = tid >> 5, lane = tid & 31;
    const int g = lane >> 2, c0 = (lane & 3) * 2;
    const int lrow = lane & 7, grp = lane >> 3;
    const int h = blockIdx.y;
    const int kv_h = h >> 2;
    const int q0 = blockIdx.x << 6;
    int ls = q0 - WINDOW_ + 1; if (ls < NMETA_) ls = NMETA_;
    const int kend = q0 + 64;
    const float scale2 = 0.088388347648318447f * 1.4426950408889634f;

#pragma unroll
    for (int it = 0; it < 8; it++) {
        int fi = tid + it * 128;
        int r = fi >> 4, q8 = fi & 15;
        size_t ga = ((size_t)(q0 + r) * NH_ + h) * HD_ + q8 * 8;
        CP_ASYNC16(smb + (u32)(r * AT_BKP + q8 * 8) * 2, (const char*)(q16 + ga));
    }
    CP_COMMIT(); CP_WAIT0();
    __syncthreads();

    u32 qf[8][4];
#pragma unroll
    for (int ks = 0; ks < 8; ks++) {
        u32 off = (u32)((w * 16 + (grp & 1) * 8 + lrow) * AT_BKP
                        + ks * 16 + (grp >> 1) * 8) * 2;
        ldsm_x4(qf[ks], smb + off);
    }
    __syncthreads();

    auto load_tile = [&](int t, int stage) {
        int kb = (t == 0) ? 0 : (ls + ((t - 1) << 6));
        int kc = (t == 0) ? NMETA_ : (kend - kb);
        if (kc > 64) kc = 64;
        u32 sK = smb + (u32)(stage * AT_STAGE) * 2;
        u32 sV = sK + AT_TILE * 2;
#pragma unroll
        for (int it = 0; it < 8; it++) {
            int fi = tid + it * 128;
            int r = fi >> 4, q8 = fi & 15;
            int sz = (r < kc) ? 16 : 0;
            int rr = (r < kc) ? r : 0;
            size_t base = (size_t)(kb + rr) * 1024 + kv_h * 128 + q8 * 8;
            u32 off = (u32)(r * AT_BKP + q8 * 8) * 2;
            CP_ASYNC16Z(sK + off, (const char*)(kv16 + base), sz);
            CP_ASYNC16Z(sV + off, (const char*)(kv16 + base + 512), sz);
        }
    };

    float m0 = -1e30f, m1 = -1e30f, l0 = 0.f, l1 = 0.f;
    float o[16][4];
#pragma unroll
    for (int i = 0; i < 16; i++)
#pragma unroll
        for (int e = 0; e < 4; e++) o[i][e] = 0.f;

    const int qp0 = q0 + w * 16 + g;
    const int qp1 = qp0 + 8;
    const int nT = 1 + ((kend - ls + 63) >> 6);

    load_tile(0, 0); CP_COMMIT();
    load_tile(1, 1); CP_COMMIT();

    for (int t = 0; t < nT; t++) {
        if (t + 1 < nT) CP_WAIT1(); else CP_WAIT0();
        __syncthreads();
        if (t + 2 < nT) {
            load_tile(t + 2, (t + 2) % 3);
            CP_COMMIT();
        }

        const u32 sK = smb + (u32)((t % 3) * AT_STAGE) * 2;
        const u32 sV = sK + AT_TILE * 2;

        if (t == 0) {
            float s[2][4];
#pragma unroll
            for (int nf = 0; nf < 2; nf++)
#pragma unroll
                for (int e = 0; e < 4; e++) s[nf][e] = 0.f;

#pragma unroll
            for (int ks = 0; ks < 8; ks++) {
                const int kk = ks * 16;
                u32 off = (u32)(((grp >> 1) * 8 + lrow) * AT_BKP
                                + kk + (grp & 1) * 8) * 2;
                u32 k2[4];
                ldsm_x4(k2, sK + off);
                mma16816(s[0], qf[ks], &k2[0]);
                mma16816(s[1], qf[ks], &k2[2]);
            }

            float mx0 = -1e30f, mx1 = -1e30f;
#pragma unroll
            for (int nf = 0; nf < 2; nf++) {
#pragma unroll
                for (int e = 0; e < 4; e++) {
                    int col = nf * 8 + c0 + (e & 1);
                    int qp = (e < 2) ? qp0 : qp1;
                    bool ok = (col <= qp);
                    float v = ok ? s[nf][e] * scale2 : -1e30f;
                    s[nf][e] = v;
                    if (e < 2) mx0 = fmaxf(mx0, v); else mx1 = fmaxf(mx1, v);
                }
            }
            mx0 = fmaxf(mx0, __shfl_xor_sync(0xffffffffu, mx0, 1));
            mx0 = fmaxf(mx0, __shfl_xor_sync(0xffffffffu, mx0, 2));
            mx1 = fmaxf(mx1, __shfl_xor_sync(0xffffffffu, mx1, 1));
            mx1 = fmaxf(mx1, __shfl_xor_sync(0xffffffffu, mx1, 2));

            float mn0 = fmaxf(m0, mx0), mn1 = fmaxf(m1, mx1);
            float rs0 = 0.f, rs1 = 0.f;
#pragma unroll
            for (int nf = 0; nf < 2; nf++) {
                float p0 = exp2f(s[nf][0] - mn0);
                float p1 = exp2f(s[nf][1] - mn0);
                float p2 = exp2f(s[nf][2] - mn1);
                float p3 = exp2f(s[nf][3] - mn1);
                s[nf][0] = p0; s[nf][1] = p1; s[nf][2] = p2; s[nf][3] = p3;
                rs0 += p0 + p1; rs1 += p2 + p3;
            }
            rs0 += __shfl_xor_sync(0xffffffffu, rs0, 1);
            rs0 += __shfl_xor_sync(0xffffffffu, rs0, 2);
            rs1 += __shfl_xor_sync(0xffffffffu, rs1, 1);
            rs1 += __shfl_xor_sync(0xffffffffu, rs1, 2);
            l0 = rs0; m0 = mn0;
            l1 = rs1; m1 = mn1;

            u32 ph[4];
            ph[0] = packh2(s[0][0], s[0][1]);
            ph[1] = packh2(s[0][2], s[0][3]);
            ph[2] = packh2(s[1][0], s[1][1]);
            ph[3] = packh2(s[1][2], s[1][3]);
#pragma unroll
            for (int nfp = 0; nfp < 8; nfp++) {
                u32 off = (u32)(((grp & 1) * 8 + lrow) * AT_BKP
                                + nfp * 16 + (grp >> 1) * 8) * 2;
                u32 v2[4];
                ldsm_x4_t(v2, sV + off);
                mma16816(o[2 * nfp],     ph, &v2[0]);
                mma16816(o[2 * nfp + 1], ph, &v2[2]);
            }
            continue;
        }

        const int kbase = ls + ((t - 1) << 6);
        int kcnt = kend - kbase;
        if (kcnt > 64) kcnt = 64;

        float s[8][4];
#pragma unroll
        for (int nf = 0; nf < 8; nf++)
#pragma unroll
            for (int e = 0; e < 4; e++) s[nf][e] = 0.f;

#pragma unroll
        for (int ks = 0; ks < 8; ks++) {
            const int kk = ks * 16;
#pragma unroll
            for (int nfp = 0; nfp < 4; nfp++) {
                u32 off = (u32)((nfp * 16 + (grp >> 1) * 8 + lrow) * AT_BKP
                                + kk + (grp & 1) * 8) * 2;
                u32 k2[4];
                ldsm_x4(k2, sK + off);
                mma16816(s[2 * nfp],     qf[ks], &k2[0]);
                mma16816(s[2 * nfp + 1], qf[ks], &k2[2]);
            }
        }

        float mx0 = -1e30f, mx1 = -1e30f;
        const bool fullv = (kbase + 64 <= q0) && (kbase >= q0 - 448);
        if (fullv) {
#pragma unroll
            for (int nf = 0; nf < 8; nf++) {
#pragma unroll
                for (int e = 0; e < 4; e++) {
                    float v = s[nf][e] * scale2;
                    s[nf][e] = v;
                    if (e < 2) mx0 = fmaxf(mx0, v); else mx1 = fmaxf(mx1, v);
                }
            }
        } else {
#pragma unroll
            for (int nf = 0; nf < 8; nf++) {
#pragma unroll
                for (int e = 0; e < 4; e++) {
                    int col = nf * 8 + c0 + (e & 1);
                    int kpos = kbase + col;
                    int qp = (e < 2) ? qp0 : qp1;
                    bool ok = (col < kcnt) && (kpos <= qp) &&
                              ((kpos >= qp - (WINDOW_ - 1)) || (kpos < NMETA_));
                    float v = ok ? s[nf][e] * scale2 : -1e30f;
                    s[nf][e] = v;
                    if (e < 2) mx0 = fmaxf(mx0, v); else mx1 = fmaxf(mx1, v);
                }
            }
        }
        mx0 = fmaxf(mx0, __shfl_xor_sync(0xffffffffu, mx0, 1));
        mx0 = fmaxf(mx0, __shfl_xor_sync(0xffffffffu, mx0, 2));
        mx1 = fmaxf(mx1, __shfl_xor_sync(0xffffffffu, mx1, 1));
        mx1 = fmaxf(mx1, __shfl_xor_sync(0xffffffffu, mx1, 2));

        float mn0 = fmaxf(m0, mx0), mn1 = fmaxf(m1, mx1);
        float f0 = exp2f(m0 - mn0), f1 = exp2f(m1 - mn1);
        float rs0 = 0.f, rs1 = 0.f;
#pragma unroll
        for (int nf = 0; nf < 8; nf++) {
            float p0 = exp2f(s[nf][0] - mn0);
            float p1 = exp2f(s[nf][1] - mn0);
            float p2 = exp2f(s[nf][2] - mn1);
            float p3 = exp2f(s[nf][3] - mn1);
            s[nf][0] = p0; s[nf][1] = p1; s[nf][2] = p2; s[nf][3] = p3;
            rs0 += p0 + p1; rs1 += p2 + p3;
        }
        rs0 += __shfl_xor_sync(0xffffffffu, rs0, 1);
        rs0 += __shfl_xor_sync(0xffffffffu, rs0, 2);
        rs1 += __shfl_xor_sync(0xffffffffu, rs1, 1);
        rs1 += __shfl_xor_sync(0xffffffffu, rs1, 2);
        l0 = l0 * f0 + rs0; m0 = mn0;
        l1 = l1 * f1 + rs1; m1 = mn1;
#pragma unroll
        for (int nf = 0; nf < 16; nf++) {
            o[nf][0] *= f0; o[nf][1] *= f0;
            o[nf][2] *= f1; o[nf][3] *= f1;
        }

#pragma unroll
        for (int ks = 0; ks < 4; ks++) {
            u32 ph[4];
            ph[0] = packh2(s[2 * ks][0],     s[2 * ks][1]);
            ph[1] = packh2(s[2 * ks][2],     s[2 * ks][3]);
            ph[2] = packh2(s[2 * ks + 1][0], s[2 * ks + 1][1]);
            ph[3] = packh2(s[2 * ks + 1][2], s[2 * ks + 1][3]);
            const int kk = ks * 16;
#pragma unroll
            for (int nfp = 0; nfp < 8; nfp++) {
                u32 off = (u32)((kk + (grp & 1) * 8 + lrow) * AT_BKP
                                + nfp * 16 + (grp >> 1) * 8) * 2;
                u32 v2[4];
                ldsm_x4_t(v2, sV + off);
                mma16816(o[2 * nfp],     ph, &v2[0]);
                mma16816(o[2 * nfp + 1], ph, &v2[2]);
            }
        }
    }

    float i0 = 1.0f / l0, i1 = 1.0f / l1;
    const int row0 = q0 + w * 16 + g;
#pragma unroll
    for (int nf = 0; nf < 16; nf++) {
        int col = nf * 8 + c0;
        size_t a0 = ((size_t)row0 * NH_ + h) * HD_ + col;
        size_t a1 = ((size_t)(row0 + 8) * NH_ + h) * HD_ + col;
        *(u32*)(y16 + a0) = packh2(o[nf][0] * i0, o[nf][1] * i0);
        *(u32*)(y16 + a1) = packh2(o[nf][2] * i1, o[nf][3] * i1);
    }
}

// ---------------------------------------------------------------------------
// Launch: two-stream batch pipeline (fork/join inside graph capture).
// ---------------------------------------------------------------------------
extern "C" void kernel_launch(void* const* d_in, const int* in_sizes, int n_in,
                              void* d_out, int out_size)
{
    const float* x   = (const float*)d_in[0];
    const float* Wq  = (const float*)d_in[1];
    const float* bq  = (const float*)d_in[2];
    const float* Wkv = (const float*)d_in[3];
    const float* bkv = (const float*)d_in[4];
    const float* Wo  = (const float*)d_in[5];
    const float* bo  = (const float*)d_in[6];
    float* out = (float*)d_out;

    __half *x16, *q16, *kv16, *y16, *wqkvt, *wot;
    float *bqkv;
    float2* tab;
    cudaGetSymbolAddress((void**)&x16,   g_x16);
    cudaGetSymbolAddress((void**)&q16,   g_q16);
    cudaGetSymbolAddress((void**)&kv16,  g_kv16);
    cudaGetSymbolAddress((void**)&y16,   g_y16);
    cudaGetSymbolAddress((void**)&wqkvt, g_wqkvt);
    cudaGetSymbolAddress((void**)&wot,   g_wot);
    cudaGetSymbolAddress((void**)&bqkv,  g_bqkv);
    cudaGetSymbolAddress((void**)&tab,   g_ropetab);

    static cudaStream_t s2 = nullptr;
    static cudaEvent_t evp = nullptr, evd = nullptr;
    if (!s2) {
        cudaStreamCreateWithFlags(&s2, cudaStreamNonBlocking);
        cudaEventCreateWithFlags(&evp, cudaEventDisableTiming);
        cudaEventCreateWithFlags(&evd, cudaEventDisableTiming);
    }

    cudaFuncSetAttribute(mma_gemm_kernel, cudaFuncAttributeMaxDynamicSharedMemorySize,
                         GT_SMEM);
    cudaFuncSetAttribute(attn_mma_kernel, cudaFuncAttributeMaxDynamicSharedMemorySize,
                         ATT_SMEM);

    const int Mh = S_;   // rows per batch

    // Prep on the main (capture-origin) stream
    prep_kernel<<<dim3(64, 64, 5), dim3(32, 8)>>>(
        x, Wq, Wkv, Wo, bq, bkv, x16, wqkvt, wot, bqkv, tab);
    cudaEventRecord(evp, 0);

    // --- Batch 0 chain on main stream ---
    mma_gemm_kernel<<<dim3(QKVN_ / 128, Mh / 128), 128, GT_SMEM>>>(
        x16, wqkvt, bqkv, nullptr, q16, kv16, tab, Mh, QKVN_, E_, 1);
    attn_mma_kernel<<<dim3(S_ / 64, NH_), 128, ATT_SMEM>>>(q16, kv16, y16);
    mma_gemm_kernel<<<dim3(E_ / 128, Mh / 128), 128, GT_SMEM>>>(
        y16, wot, bo, out, nullptr, nullptr, tab, Mh, E_, E_, 0);

    // --- Batch 1 chain on forked stream s2 ---
    cudaStreamWaitEvent(s2, evp, 0);
    const size_t oQ = (size_t)S_ * E_, oKV = (size_t)S_ * KVOUT_;
    mma_gemm_kernel<<<dim3(QKVN_ / 128, Mh / 128), 128, GT_SMEM, s2>>>(
        x16 + oQ, wqkvt, bqkv, nullptr, q16 + oQ, kv16 + oKV, tab, Mh, QKVN_, E_, 1);
    attn_mma_kernel<<<dim3(S_ / 64, NH_), 128, ATT_SMEM, s2>>>(
        q16 + oQ, kv16 + oKV, y16 + oQ);
    mma_gemm_kernel<<<dim3(E_ / 128, Mh / 128), 128, GT_SMEM, s2>>>(
        y16 + oQ, wot, bo, out + oQ, nullptr, nullptr, tab, Mh, E_, E_, 0);
    cudaEventRecord(evd, s2);

    // Join back to the main stream
    cudaStreamWaitEvent(0, evd, 0);
}